// round 1
// baseline (speedup 1.0000x reference)
#include <cuda_runtime.h>
#include <cuda_bf16.h>

// ---------------------------------------------------------------------------
// LSTM Seq2Seq: enc 2-layer x 96 steps, dec 2-layer x 24 steps, B=512, H=512
// Strategy: per (step,layer) one fused GEMM(512x2048xK)+LSTM-cell kernel.
// Weights pre-packed (per launch) into k-major, gate-interleaved layout so the
// cell fuses into the GEMM epilogue (each thread owns all 4 gates of a j).
// ---------------------------------------------------------------------------

#define HIDDEN   512
#define BATCH    512
#define NFEAT    32
#define LAGS     96
#define HORIZONS 24
#define NGATE    2048  // 4*HIDDEN

// ---- scratch layout (floats) ----
#define OFF_WP_ENC0  0
#define SZ_WP0       (544 * 2048)         // (32+512) x 2048
#define OFF_WP_ENC1  (OFF_WP_ENC0 + SZ_WP0)
#define SZ_WP1       (1024 * 2048)        // (512+512) x 2048
#define OFF_WP_DEC0  (OFF_WP_ENC1 + SZ_WP1)
#define OFF_WP_DEC1  (OFF_WP_DEC0 + SZ_WP0)
#define OFF_BS       (OFF_WP_DEC1 + SZ_WP1)   // 4 x 2048
#define OFF_H        (OFF_BS + 4 * 2048)      // [2 layer][2 pp][512*512]
#define OFF_C        (OFF_H + 2 * 2 * BATCH * HIDDEN)  // [2 layer][512*512]
#define OFF_DECX     (OFF_C + 2 * BATCH * HIDDEN)      // 512*32
#define SCRATCH_FLOATS (OFF_DECX + BATCH * NFEAT)

__device__ float g_scratch[SCRATCH_FLOATS];

// ---------------------------------------------------------------------------
// Weight packing: Wp[k][j*4+g] = (k<in_dim ? Wih[g*512+j][k] : Whh[g*512+j][k-in_dim])
// ---------------------------------------------------------------------------
__global__ void pack_weights(const float* __restrict__ Wih,
                             const float* __restrict__ Whh,
                             int in_dim, float* __restrict__ Wp, int total)
{
    int idx = blockIdx.x * blockDim.x + threadIdx.x;
    if (idx >= total) return;
    int k = idx / NGATE;
    int n = idx - k * NGATE;
    int j = n >> 2, g = n & 3;
    float v;
    if (k < in_dim) v = Wih[(g * HIDDEN + j) * in_dim + k];
    else            v = Whh[(g * HIDDEN + j) * HIDDEN + (k - in_dim)];
    Wp[idx] = v;
}

__global__ void pack_bias(const float* __restrict__ bih,
                          const float* __restrict__ bhh,
                          float* __restrict__ bs)
{
    int n = blockIdx.x * blockDim.x + threadIdx.x;
    if (n >= NGATE) return;
    int j = n >> 2, g = n & 3;
    bs[n] = bih[g * HIDDEN + j] + bhh[g * HIDDEN + j];
}

__global__ void zero_fill(float* __restrict__ p, int n)
{
    int i = blockIdx.x * blockDim.x + threadIdx.x;
    if (i < n) p[i] = 0.f;
}

// decx[b][f] = src[b][95][f]
__global__ void init_decx(const float* __restrict__ src, float* __restrict__ decx)
{
    int i = blockIdx.x * blockDim.x + threadIdx.x;
    if (i >= BATCH * NFEAT) return;
    int b = i / NFEAT, f = i - b * NFEAT;
    decx[i] = src[b * (LAGS * NFEAT) + (LAGS - 1) * NFEAT + f];
}

// ---------------------------------------------------------------------------
// Fused GEMM + LSTM cell.
//   A[b][k] = (k < IN_DIM) ? x[b*x_stride + k] : h_in[b*512 + k-IN_DIM]
//   z[b][j*4+g] = sum_k A[b][k] * Wp[k][j*4+g] + bs[j*4+g]
//   cell update -> c (in place), h_out
// Tile: BM=64 (batch), BN=64 (n=j*4+g -> 16 j per block), BK=16, 256 threads,
// each thread 4x4 accumulators = 4 batch rows x 1 j x 4 gates.
// ---------------------------------------------------------------------------
#define BM 64
#define BN 64
#define BK 16

__device__ __forceinline__ float fsigmoid(float x) {
    return 1.f / (1.f + __expf(-x));
}
__device__ __forceinline__ float ftanh(float x) {
    return 2.f / (1.f + __expf(-2.f * x)) - 1.f;
}

template <int IN_DIM>
__global__ __launch_bounds__(256)
void lstm_gemm_cell(const float* __restrict__ xA, int x_stride,
                    const float* __restrict__ hA,
                    const float* __restrict__ Wp,
                    const float* __restrict__ bs,
                    float* __restrict__ cst,
                    float* __restrict__ h_out)
{
    constexpr int K = IN_DIM + HIDDEN;
    __shared__ float As[BK][BM + 4];
    __shared__ float Bs[BK][BN];

    const int tid = threadIdx.x;
    const int bm = blockIdx.y, bn = blockIdx.x;
    const int tn = tid & 15;        // 0..15 -> j within block
    const int tm = tid >> 4;        // 0..15 -> batch group

    float acc[4][4];
#pragma unroll
    for (int i = 0; i < 4; i++)
#pragma unroll
        for (int jv = 0; jv < 4; jv++) acc[i][jv] = 0.f;

    for (int kt = 0; kt < K; kt += BK) {
        // load A tile: As[kk][m]
#pragma unroll
        for (int p = 0; p < 4; ++p) {
            int idx = tid + p * 256;
            int m = idx >> 4, kk = idx & 15;
            int b = bm * BM + m;
            int k = kt + kk;
            float v;
            if (k < IN_DIM) v = xA[b * x_stride + k];
            else            v = hA[b * HIDDEN + (k - IN_DIM)];
            As[kk][m] = v;
        }
        // load B tile: Bs[kk][n]  (coalesced over n)
#pragma unroll
        for (int p = 0; p < 4; ++p) {
            int idx = tid + p * 256;
            int n = idx & 63, kk = idx >> 6;
            Bs[kk][n] = Wp[(kt + kk) * NGATE + bn * BN + n];
        }
        __syncthreads();

#pragma unroll
        for (int kk = 0; kk < BK; ++kk) {
            float4 a = *reinterpret_cast<const float4*>(&As[kk][tm * 4]);
            float4 w = *reinterpret_cast<const float4*>(&Bs[kk][tn * 4]);
            float av[4] = {a.x, a.y, a.z, a.w};
            float wv[4] = {w.x, w.y, w.z, w.w};
#pragma unroll
            for (int mi = 0; mi < 4; ++mi)
#pragma unroll
                for (int ni = 0; ni < 4; ++ni)
                    acc[mi][ni] = fmaf(av[mi], wv[ni], acc[mi][ni]);
        }
        __syncthreads();
    }

    // epilogue: LSTM cell for j = bn*16 + tn, batch rows bm*64 + tm*4 + mi
    const int j = bn * 16 + tn;
    const float bi = bs[j * 4 + 0];
    const float bf = bs[j * 4 + 1];
    const float bg = bs[j * 4 + 2];
    const float bo = bs[j * 4 + 3];
#pragma unroll
    for (int mi = 0; mi < 4; ++mi) {
        int b = bm * BM + tm * 4 + mi;
        float zi = acc[mi][0] + bi;
        float zf = acc[mi][1] + bf;
        float zg = acc[mi][2] + bg;
        float zo = acc[mi][3] + bo;
        float si = fsigmoid(zi);
        float sf = fsigmoid(zf);
        float so = fsigmoid(zo);
        float tg = ftanh(zg);
        float cn = sf * cst[b * HIDDEN + j] + si * tg;
        cst[b * HIDDEN + j] = cn;
        h_out[b * HIDDEN + j] = so * ftanh(cn);
    }
}

// ---------------------------------------------------------------------------
// Decoder heads: out[b*24+t] = h1[b]·fc1_w + fc1_b ; decx[b][f] = h1[b]·fc4_w[f] + fc4_b[f]
// ---------------------------------------------------------------------------
__global__ __launch_bounds__(256)
void dec_fc(const float* __restrict__ h1,
            const float* __restrict__ fc1_w, const float* __restrict__ fc1_b,
            const float* __restrict__ fc4_w, const float* __restrict__ fc4_b,
            float* __restrict__ out, int t, float* __restrict__ decx)
{
    __shared__ float sh[HIDDEN];
    const int b = blockIdx.x;
    for (int i = threadIdx.x; i < HIDDEN; i += blockDim.x)
        sh[i] = h1[b * HIDDEN + i];
    __syncthreads();

    const int warp = threadIdx.x >> 5;
    const int lane = threadIdx.x & 31;
    for (int o = warp; o < 1 + NFEAT; o += 8) {
        const float* w = (o == 0) ? fc1_w : (fc4_w + (o - 1) * HIDDEN);
        float s = 0.f;
#pragma unroll 4
        for (int k = lane; k < HIDDEN; k += 32) s += sh[k] * w[k];
#pragma unroll
        for (int off = 16; off; off >>= 1) s += __shfl_down_sync(0xffffffffu, s, off);
        if (lane == 0) {
            if (o == 0) out[b * HORIZONS + t] = s + fc1_b[0];
            else        decx[b * NFEAT + (o - 1)] = s + fc4_b[o - 1];
        }
    }
}

// ---------------------------------------------------------------------------
extern "C" void kernel_launch(void* const* d_in, const int* in_sizes, int n_in,
                              void* d_out, int out_size)
{
    // input order detection: dict order has 'train' (size 1) at index 2,
    // signature order has enc_Wih0 (size 65536) there.
    const int wb = (in_sizes[2] == 1) ? 3 : 2;

    const float* src = (const float*)d_in[0];
    // weights: [enc0: Wih,Whh,bih,bhh][enc1][dec0][dec1]
    const float* W[16];
    for (int i = 0; i < 16; i++) W[i] = (const float*)d_in[wb + i];
    const float* fc1_w = (const float*)d_in[wb + 16];
    const float* fc1_b = (const float*)d_in[wb + 17];
    const float* fc4_w = (const float*)d_in[wb + 18];
    const float* fc4_b = (const float*)d_in[wb + 19];
    float* out = (float*)d_out;

    float* S = nullptr;
    cudaGetSymbolAddress((void**)&S, g_scratch);

    float* WP[4] = {S + OFF_WP_ENC0, S + OFF_WP_ENC1, S + OFF_WP_DEC0, S + OFF_WP_DEC1};
    float* BS   = S + OFF_BS;
    float* Hst  = S + OFF_H;    // [layer][pp][B*H]
    float* Cst  = S + OFF_C;    // [layer][B*H]
    float* decx = S + OFF_DECX;

    const int in_dims[4] = {NFEAT, HIDDEN, NFEAT, HIDDEN};
    const int wp_sz[4]   = {SZ_WP0, SZ_WP1, SZ_WP0, SZ_WP1};

    // ---- pack weights + biases ----
    for (int l = 0; l < 4; l++) {
        int total = wp_sz[l];
        pack_weights<<<(total + 255) / 256, 256>>>(W[l * 4 + 0], W[l * 4 + 1],
                                                   in_dims[l], WP[l], total);
        pack_bias<<<(NGATE + 255) / 256, 256>>>(W[l * 4 + 2], W[l * 4 + 3],
                                                BS + l * NGATE);
    }

    // ---- zero states (h pingpong + c) ----
    {
        int n = 2 * 2 * BATCH * HIDDEN + 2 * BATCH * HIDDEN;
        zero_fill<<<(n + 255) / 256, 256>>>(Hst, n);
    }

    dim3 grid(NGATE / BN, BATCH / BM);  // (32, 8)
    const int BH = BATCH * HIDDEN;

    // ---- encoder: 96 steps ----
    for (int t = 0; t < LAGS; t++) {
        const float* h0_in = Hst + (0 * 2 + (t & 1)) * BH;
        float*       h0_out = Hst + (0 * 2 + ((t + 1) & 1)) * BH;
        const float* h1_in = Hst + (2 + (t & 1)) * BH;
        float*       h1_out = Hst + (2 + ((t + 1) & 1)) * BH;

        lstm_gemm_cell<NFEAT><<<grid, 256>>>(src + t * NFEAT, LAGS * NFEAT,
                                             h0_in, WP[0], BS + 0 * NGATE,
                                             Cst + 0 * BH, h0_out);
        lstm_gemm_cell<HIDDEN><<<grid, 256>>>(h0_out, HIDDEN,
                                              h1_in, WP[1], BS + 1 * NGATE,
                                              Cst + 1 * BH, h1_out);
    }

    // ---- decoder: 24 steps (states continue from encoder) ----
    init_decx<<<(BATCH * NFEAT + 255) / 256, 256>>>(src, decx);

    for (int tt = 0; tt < HORIZONS; tt++) {
        int t = LAGS + tt;
        const float* h0_in = Hst + (0 * 2 + (t & 1)) * BH;
        float*       h0_out = Hst + (0 * 2 + ((t + 1) & 1)) * BH;
        const float* h1_in = Hst + (2 + (t & 1)) * BH;
        float*       h1_out = Hst + (2 + ((t + 1) & 1)) * BH;

        lstm_gemm_cell<NFEAT><<<grid, 256>>>(decx, NFEAT,
                                             h0_in, WP[2], BS + 2 * NGATE,
                                             Cst + 0 * BH, h0_out);
        lstm_gemm_cell<HIDDEN><<<grid, 256>>>(h0_out, HIDDEN,
                                              h1_in, WP[3], BS + 3 * NGATE,
                                              Cst + 1 * BH, h1_out);
        dec_fc<<<BATCH, 256>>>(h1_out, fc1_w, fc1_b, fc4_w, fc4_b, out, tt, decx);
    }
}

// round 3
// speedup vs baseline: 2.9154x; 2.9154x over previous
#include <cuda_runtime.h>
#include <cuda_bf16.h>
#include <cstdint>

// ---------------------------------------------------------------------------
// LSTM Seq2Seq on GB300 (sm_103 base target -> warp-level HMMA path).
// Per (step,layer): fused tf32 mma.sync GEMM + LSTM cell.
//   z[b][n] = sum_k A[b][k] * Wp[n][k],  n = j*4+g (gate-interleaved)
// CTA tile 64x128, BK=32, 4-stage cp.async pipeline, 8 warps x (32x32).
// Epilogue: accs -> SMEM z-tile -> cell -> h (tf32-rounded), c (fp32).
// ---------------------------------------------------------------------------

#define HIDDEN   512
#define BATCH    512
#define NFEAT    32
#define LAGS     96
#define HORIZONS 24
#define NGATE    2048

// ---- scratch layout (floats) ----
#define OFF_WP_ENC0  0
#define SZ_WP0       (544 * 2048)
#define OFF_WP_ENC1  (OFF_WP_ENC0 + SZ_WP0)
#define SZ_WP1       (1024 * 2048)
#define OFF_WP_DEC0  (OFF_WP_ENC1 + SZ_WP1)
#define OFF_WP_DEC1  (OFF_WP_DEC0 + SZ_WP0)
#define OFF_BS       (OFF_WP_DEC1 + SZ_WP1)
#define OFF_H        (OFF_BS + 4 * 2048)
#define OFF_C        (OFF_H + 2 * 2 * BATCH * HIDDEN)
#define OFF_DECX     (OFF_C + 2 * BATCH * HIDDEN)
#define SCRATCH_FLOATS (OFF_DECX + BATCH * NFEAT)

__device__ float g_scratch[SCRATCH_FLOATS];

// ---------------------------------------------------------------------------
// helpers
// ---------------------------------------------------------------------------
__device__ __forceinline__ uint32_t smem_u32(const void* p) {
    return (uint32_t)__cvta_generic_to_shared(p);
}

__device__ __forceinline__ void cpa16(uint32_t dst, const void* src) {
    asm volatile("cp.async.cg.shared.global [%0], [%1], 16;" :: "r"(dst), "l"(src));
}
__device__ __forceinline__ void cpa_commit() {
    asm volatile("cp.async.commit_group;" ::: "memory");
}

__device__ __forceinline__ void mma_tf32(float* d, const uint32_t* a,
                                         uint32_t b0, uint32_t b1) {
    asm volatile(
        "mma.sync.aligned.m16n8k8.row.col.f32.tf32.tf32.f32 "
        "{%0,%1,%2,%3},{%4,%5,%6,%7},{%8,%9},{%0,%1,%2,%3};"
        : "+f"(d[0]), "+f"(d[1]), "+f"(d[2]), "+f"(d[3])
        : "r"(a[0]), "r"(a[1]), "r"(a[2]), "r"(a[3]), "r"(b0), "r"(b1));
}

__device__ __forceinline__ float tf32r(float v) {
    uint32_t b;
    asm("cvt.rna.tf32.f32 %0, %1;" : "=r"(b) : "f"(v));
    return __uint_as_float(b);
}

__device__ __forceinline__ float fsigmoid(float x) { return 1.f / (1.f + __expf(-x)); }
__device__ __forceinline__ float ftanh(float x)    { return 2.f / (1.f + __expf(-2.f * x)) - 1.f; }

// ---------------------------------------------------------------------------
// Aux kernels
// ---------------------------------------------------------------------------
__global__ void pack_weights(const float* __restrict__ Wih,
                             const float* __restrict__ Whh,
                             int in_dim, int Ktot, float* __restrict__ Wp, int total)
{
    int idx = blockIdx.x * blockDim.x + threadIdx.x;
    if (idx >= total) return;
    int n = idx / Ktot;
    int k = idx - n * Ktot;
    int j = n >> 2, g = n & 3;
    float v;
    if (k < in_dim) v = Wih[(g * HIDDEN + j) * in_dim + k];
    else            v = Whh[(g * HIDDEN + j) * HIDDEN + (k - in_dim)];
    Wp[idx] = tf32r(v);
}

__global__ void pack_bias(const float* __restrict__ bih,
                          const float* __restrict__ bhh,
                          float* __restrict__ bs)
{
    int n = blockIdx.x * blockDim.x + threadIdx.x;
    if (n >= NGATE) return;
    int j = n >> 2, g = n & 3;
    bs[n] = bih[g * HIDDEN + j] + bhh[g * HIDDEN + j];
}

__global__ void zero_fill(float* __restrict__ p, int n)
{
    int i = blockIdx.x * blockDim.x + threadIdx.x;
    if (i < n) p[i] = 0.f;
}

__global__ void init_decx(const float* __restrict__ src, float* __restrict__ decx)
{
    int i = blockIdx.x * blockDim.x + threadIdx.x;
    if (i >= BATCH * NFEAT) return;
    int b = i / NFEAT, f = i - b * NFEAT;
    decx[i] = src[b * (LAGS * NFEAT) + (LAGS - 1) * NFEAT + f];
}

// ---------------------------------------------------------------------------
// Fused tf32 mma.sync GEMM + LSTM cell.
// grid(16, 8): bn = N tile (128 cols of n), bm = M tile (64 batch rows)
// SMEM per stage: A 64x36 fl (9216B) + B 128x36 fl (18432B) = 27648B, x4 stages.
// ---------------------------------------------------------------------------
#define STAGE_B   27648
#define A_STRIDE  36
#define DYN_SMEM  (4 * STAGE_B)

template <int IN_DIM>
__global__ __launch_bounds__(256, 1)
void lstm_step_mma(const float* __restrict__ xA, int xs,
                   const float* __restrict__ hA,
                   const float* __restrict__ Wpk,
                   const float* __restrict__ bs,
                   float* __restrict__ cst,
                   float* __restrict__ h_out)
{
    constexpr int K = IN_DIM + HIDDEN;
    constexpr int T = K / 32;

    extern __shared__ char smem[];

    const int tid  = threadIdx.x;
    const int bn   = blockIdx.x, bm = blockIdx.y;
    const int w    = tid >> 5, lane = tid & 31;
    const int g    = lane >> 2, tg = lane & 3;
    const int wm0  = (w >> 2) * 32;     // warp m offset (0/32)
    const int wn0  = (w & 3) * 32;      // warp n offset (0/32/64/96)

    // ---- stage issue ----
    auto issue = [&](int t) {
        const int s = t & 3;
        char* aB = smem + s * STAGE_B;
        char* bB = aB + 9216;
        const int k0 = t * 32;
        const float* sA;
        int stride;
        if (k0 < IN_DIM) { sA = xA + k0;            stride = xs;     }
        else             { sA = hA + (k0 - IN_DIM); stride = HIDDEN; }
#pragma unroll
        for (int p = 0; p < 2; ++p) {               // A: 64 rows x 8 float4
            int i   = tid + p * 256;
            int row = i >> 3, c4 = i & 7;
            cpa16(smem_u32(aB + row * 144 + c4 * 16),
                  sA + (bm * 64 + row) * stride + c4 * 4);
        }
#pragma unroll
        for (int p = 0; p < 4; ++p) {               // B: 128 rows x 8 float4
            int i   = tid + p * 256;
            int row = i >> 3, c4 = i & 7;
            cpa16(smem_u32(bB + row * 144 + c4 * 16),
                  Wpk + (bn * 128 + row) * K + k0 + c4 * 4);
        }
        cpa_commit();
    };

    float acc[2][4][4];
#pragma unroll
    for (int mf = 0; mf < 2; ++mf)
#pragma unroll
        for (int nf = 0; nf < 4; ++nf)
#pragma unroll
            for (int q = 0; q < 4; ++q) acc[mf][nf][q] = 0.f;

    issue(0); issue(1); issue(2);

    for (int t = 0; t < T; ++t) {
        if (t < T - 2) asm volatile("cp.async.wait_group 2;" ::: "memory");
        else           asm volatile("cp.async.wait_group 0;" ::: "memory");
        __syncthreads();

        const int s = t & 3;
        const uint32_t* As = (const uint32_t*)(smem + s * STAGE_B);
        const uint32_t* Bs = (const uint32_t*)(smem + s * STAGE_B + 9216);

#pragma unroll
        for (int kk = 0; kk < 4; ++kk) {
            const int kb = kk * 8 + tg;
            uint32_t a[2][4];
#pragma unroll
            for (int mf = 0; mf < 2; ++mf) {
                const int r0 = wm0 + mf * 16 + g;
                a[mf][0] = As[r0 * A_STRIDE + kb];
                a[mf][1] = As[(r0 + 8) * A_STRIDE + kb];
                a[mf][2] = As[r0 * A_STRIDE + kb + 4];
                a[mf][3] = As[(r0 + 8) * A_STRIDE + kb + 4];
            }
#pragma unroll
            for (int nf = 0; nf < 4; ++nf) {
                const int nr = wn0 + nf * 8 + g;
                uint32_t b0 = Bs[nr * A_STRIDE + kb];
                uint32_t b1 = Bs[nr * A_STRIDE + kb + 4];
                mma_tf32(acc[0][nf], a[0], b0, b1);
                mma_tf32(acc[1][nf], a[1], b0, b1);
            }
        }

        __syncthreads();
        if (t + 3 < T) issue(t + 3);
    }

    // ---- epilogue: accs -> SMEM z-tile [64][132] -> fused LSTM cell ----
    __syncthreads();
    float* zs = (float*)smem;                     // 64*132 floats = 33792 B
#pragma unroll
    for (int mf = 0; mf < 2; ++mf)
#pragma unroll
        for (int nf = 0; nf < 4; ++nf) {
            int r = wm0 + mf * 16 + g;
            int c = wn0 + nf * 8 + 2 * tg;
            *(float2*)&zs[r * 132 + c]       = make_float2(acc[mf][nf][0], acc[mf][nf][1]);
            *(float2*)&zs[(r + 8) * 132 + c] = make_float2(acc[mf][nf][2], acc[mf][nf][3]);
        }
    __syncthreads();

#pragma unroll
    for (int p = 0; p < 8; ++p) {
        int idx = tid + p * 256;                  // 2048 = 64 rows x 32 j
        int bl = idx >> 5, jl = idx & 31;
        int b  = bm * 64 + bl;
        int j  = bn * 32 + jl;
        float4 z4 = *(float4*)&zs[bl * 132 + jl * 4];
        float4 b4 = *(const float4*)&bs[(bn * 32 + jl) * 4];
        float zi = z4.x + b4.x;
        float zf = z4.y + b4.y;
        float zg = z4.z + b4.z;
        float zo = z4.w + b4.w;
        float cn = fsigmoid(zf) * cst[b * HIDDEN + j] + fsigmoid(zi) * ftanh(zg);
        cst[b * HIDDEN + j]   = cn;
        h_out[b * HIDDEN + j] = tf32r(fsigmoid(zo) * ftanh(cn));
    }
}

// ---------------------------------------------------------------------------
// Decoder heads
// ---------------------------------------------------------------------------
__global__ __launch_bounds__(256)
void dec_fc(const float* __restrict__ h1,
            const float* __restrict__ fc1_w, const float* __restrict__ fc1_b,
            const float* __restrict__ fc4_w, const float* __restrict__ fc4_b,
            float* __restrict__ out, int t, float* __restrict__ decx)
{
    __shared__ float sh[HIDDEN];
    const int b = blockIdx.x;
    for (int i = threadIdx.x; i < HIDDEN; i += blockDim.x)
        sh[i] = h1[b * HIDDEN + i];
    __syncthreads();

    const int warp = threadIdx.x >> 5;
    const int lane = threadIdx.x & 31;
    for (int o = warp; o < 1 + NFEAT; o += 8) {
        const float* w = (o == 0) ? fc1_w : (fc4_w + (o - 1) * HIDDEN);
        float s = 0.f;
#pragma unroll 4
        for (int k = lane; k < HIDDEN; k += 32) s += sh[k] * w[k];
#pragma unroll
        for (int off = 16; off; off >>= 1) s += __shfl_down_sync(0xffffffffu, s, off);
        if (lane == 0) {
            if (o == 0) out[b * HORIZONS + t] = s + fc1_b[0];
            else        decx[b * NFEAT + (o - 1)] = tf32r(s + fc4_b[o - 1]);
        }
    }
}

// ---------------------------------------------------------------------------
extern "C" void kernel_launch(void* const* d_in, const int* in_sizes, int n_in,
                              void* d_out, int out_size)
{
    const int wb = (in_sizes[2] == 1) ? 3 : 2;

    const float* src = (const float*)d_in[0];
    const float* W[16];
    for (int i = 0; i < 16; i++) W[i] = (const float*)d_in[wb + i];
    const float* fc1_w = (const float*)d_in[wb + 16];
    const float* fc1_b = (const float*)d_in[wb + 17];
    const float* fc4_w = (const float*)d_in[wb + 18];
    const float* fc4_b = (const float*)d_in[wb + 19];
    float* out = (float*)d_out;

    float* S = nullptr;
    cudaGetSymbolAddress((void**)&S, g_scratch);

    float* WP[4] = {S + OFF_WP_ENC0, S + OFF_WP_ENC1, S + OFF_WP_DEC0, S + OFF_WP_DEC1};
    float* BS   = S + OFF_BS;
    float* Hst  = S + OFF_H;
    float* Cst  = S + OFF_C;
    float* decx = S + OFF_DECX;

    cudaFuncSetAttribute(lstm_step_mma<NFEAT>,
                         cudaFuncAttributeMaxDynamicSharedMemorySize, DYN_SMEM);
    cudaFuncSetAttribute(lstm_step_mma<HIDDEN>,
                         cudaFuncAttributeMaxDynamicSharedMemorySize, DYN_SMEM);

    const int in_dims[4] = {NFEAT, HIDDEN, NFEAT, HIDDEN};
    const int k_tot[4]   = {NFEAT + HIDDEN, 2 * HIDDEN, NFEAT + HIDDEN, 2 * HIDDEN};
    const int wp_sz[4]   = {SZ_WP0, SZ_WP1, SZ_WP0, SZ_WP1};

    for (int l = 0; l < 4; l++) {
        pack_weights<<<(wp_sz[l] + 255) / 256, 256>>>(W[l * 4 + 0], W[l * 4 + 1],
                                                      in_dims[l], k_tot[l], WP[l], wp_sz[l]);
        pack_bias<<<(NGATE + 255) / 256, 256>>>(W[l * 4 + 2], W[l * 4 + 3], BS + l * NGATE);
    }

    {
        int n = 2 * 2 * BATCH * HIDDEN + 2 * BATCH * HIDDEN;
        zero_fill<<<(n + 255) / 256, 256>>>(Hst, n);
    }

    dim3 grid(NGATE / 128, BATCH / 64);  // (16, 8)
    const int BH = BATCH * HIDDEN;

    for (int t = 0; t < LAGS; t++) {
        const float* h0_in  = Hst + (0 * 2 + (t & 1)) * BH;
        float*       h0_out = Hst + (0 * 2 + ((t + 1) & 1)) * BH;
        const float* h1_in  = Hst + (2 + (t & 1)) * BH;
        float*       h1_out = Hst + (2 + ((t + 1) & 1)) * BH;

        lstm_step_mma<NFEAT><<<grid, 256, DYN_SMEM>>>(src + t * NFEAT, LAGS * NFEAT,
                                                      h0_in, WP[0], BS + 0 * NGATE,
                                                      Cst + 0 * BH, h0_out);
        lstm_step_mma<HIDDEN><<<grid, 256, DYN_SMEM>>>(h0_out, HIDDEN,
                                                       h1_in, WP[1], BS + 1 * NGATE,
                                                       Cst + 1 * BH, h1_out);
    }

    init_decx<<<(BATCH * NFEAT + 255) / 256, 256>>>(src, decx);

    for (int tt = 0; tt < HORIZONS; tt++) {
        int t = LAGS + tt;
        const float* h0_in  = Hst + (0 * 2 + (t & 1)) * BH;
        float*       h0_out = Hst + (0 * 2 + ((t + 1) & 1)) * BH;
        const float* h1_in  = Hst + (2 + (t & 1)) * BH;
        float*       h1_out = Hst + (2 + ((t + 1) & 1)) * BH;

        lstm_step_mma<NFEAT><<<grid, 256, DYN_SMEM>>>(decx, NFEAT,
                                                      h0_in, WP[2], BS + 2 * NGATE,
                                                      Cst + 0 * BH, h0_out);
        lstm_step_mma<HIDDEN><<<grid, 256, DYN_SMEM>>>(h0_out, HIDDEN,
                                                       h1_in, WP[3], BS + 3 * NGATE,
                                                       Cst + 1 * BH, h1_out);
        dec_fc<<<BATCH, 256>>>(h1_out, fc1_w, fc1_b, fc4_w, fc4_b, out, tt, decx);
    }
}

// round 4
// speedup vs baseline: 4.0466x; 1.3880x over previous
#include <cuda_runtime.h>
#include <cuda_fp16.h>
#include <cstdint>

// ---------------------------------------------------------------------------
// LSTM Seq2Seq on GB300, fp16 mma.sync (m16n8k16) + fused LSTM cell.
//   z[b][n] = sum_k A[b][k] * Wp[n][k],  n = j*4+g (gate-interleaved)
// CTA tile 64x128, BK=32, 4-stage cp.async pipeline, 8 warps x (32x32).
// A/W/h in fp16 (same mantissa as tf32), c kept fp32.
// ---------------------------------------------------------------------------

#define HIDDEN   512
#define BATCH    512
#define NFEAT    32
#define LAGS     96
#define HORIZONS 24
#define NGATE    2048

// ---- byte-based scratch layout ----
#define OFF_WP0   0u
#define SZ_WP0B   (544u * 2048u * 2u)
#define OFF_WP1   (OFF_WP0 + SZ_WP0B)
#define SZ_WP1B   (1024u * 2048u * 2u)
#define OFF_WP2   (OFF_WP1 + SZ_WP1B)
#define OFF_WP3   (OFF_WP2 + SZ_WP0B)
#define OFF_BS    (OFF_WP3 + SZ_WP1B)                 // float[4*2048]
#define OFF_H     (OFF_BS + 4u * 2048u * 4u)          // half[2*2*512*512]
#define OFF_C     (OFF_H + 2u * 2u * 512u * 512u * 2u) // float[2*512*512]
#define OFF_XH    (OFF_C + 2u * 512u * 512u * 4u)     // half[96*512*32]
#define OFF_DECX  (OFF_XH + 96u * 512u * 32u * 2u)    // half[512*32]
#define SCRATCH_BYTES (OFF_DECX + 512u * 32u * 2u)

__device__ __align__(1024) unsigned char g_scratch[SCRATCH_BYTES];

// ---------------------------------------------------------------------------
__device__ __forceinline__ uint32_t smem_u32(const void* p) {
    return (uint32_t)__cvta_generic_to_shared(p);
}
__device__ __forceinline__ void cpa16(uint32_t dst, const void* src) {
    asm volatile("cp.async.cg.shared.global [%0], [%1], 16;" :: "r"(dst), "l"(src));
}
__device__ __forceinline__ void cpa_commit() {
    asm volatile("cp.async.commit_group;" ::: "memory");
}
__device__ __forceinline__ void mma_f16(float* d, const uint32_t* a,
                                        uint32_t b0, uint32_t b1) {
    asm volatile(
        "mma.sync.aligned.m16n8k16.row.col.f32.f16.f16.f32 "
        "{%0,%1,%2,%3},{%4,%5,%6,%7},{%8,%9},{%0,%1,%2,%3};"
        : "+f"(d[0]), "+f"(d[1]), "+f"(d[2]), "+f"(d[3])
        : "r"(a[0]), "r"(a[1]), "r"(a[2]), "r"(a[3]), "r"(b0), "r"(b1));
}
__device__ __forceinline__ float fsigmoid(float x) { return 1.f / (1.f + __expf(-x)); }
__device__ __forceinline__ float ftanh(float x)    { return 2.f / (1.f + __expf(-2.f * x)) - 1.f; }

// ---------------------------------------------------------------------------
// Aux kernels
// ---------------------------------------------------------------------------
__global__ void pack_weights(const float* __restrict__ Wih,
                             const float* __restrict__ Whh,
                             int in_dim, int Ktot, __half* __restrict__ Wp, int total)
{
    int idx = blockIdx.x * blockDim.x + threadIdx.x;
    if (idx >= total) return;
    int n = idx / Ktot;
    int k = idx - n * Ktot;
    int j = n >> 2, g = n & 3;
    float v;
    if (k < in_dim) v = Wih[(g * HIDDEN + j) * in_dim + k];
    else            v = Whh[(g * HIDDEN + j) * HIDDEN + (k - in_dim)];
    Wp[idx] = __float2half_rn(v);
}

__global__ void pack_bias(const float* __restrict__ bih,
                          const float* __restrict__ bhh,
                          float* __restrict__ bs)
{
    int n = blockIdx.x * blockDim.x + threadIdx.x;
    if (n >= NGATE) return;
    int j = n >> 2, g = n & 3;
    bs[n] = bih[g * HIDDEN + j] + bhh[g * HIDDEN + j];
}

// src [B][LAGS][32] fp32 -> xh [LAGS][B][32] half
__global__ void convert_src(const float* __restrict__ src, __half* __restrict__ xh)
{
    int i = blockIdx.x * blockDim.x + threadIdx.x;
    if (i >= LAGS * BATCH * NFEAT) return;
    int t = i / (BATCH * NFEAT);
    int r = i - t * (BATCH * NFEAT);
    int b = r / NFEAT, f = r - b * NFEAT;
    xh[i] = __float2half_rn(src[b * (LAGS * NFEAT) + t * NFEAT + f]);
}

__global__ void zero_h(__half* __restrict__ p, int n)
{
    int i = blockIdx.x * blockDim.x + threadIdx.x;
    if (i < n) p[i] = __half(0.f);
}
__global__ void zero_f(float* __restrict__ p, int n)
{
    int i = blockIdx.x * blockDim.x + threadIdx.x;
    if (i < n) p[i] = 0.f;
}

__global__ void init_decx(const float* __restrict__ src, __half* __restrict__ decx)
{
    int i = blockIdx.x * blockDim.x + threadIdx.x;
    if (i >= BATCH * NFEAT) return;
    int b = i / NFEAT, f = i - b * NFEAT;
    decx[i] = __float2half_rn(src[b * (LAGS * NFEAT) + (LAGS - 1) * NFEAT + f]);
}

// ---------------------------------------------------------------------------
// Fused fp16 GEMM + LSTM cell.
// grid(16, 8): bn = N tile (128 n-cols), bm = M tile (64 batch rows)
// SMEM stage: A 64 rows x 96B + B 128 rows x 96B = 18432B, 4 stages = 73728B.
// Row layout: row r data (32 halves = 4 chunks of 16B) at
//   r*96 + ((r>>2)&1)*16 + chunk*16   -> all fragment loads bank-conflict-free.
// ---------------------------------------------------------------------------
#define ROW_B    96
#define A_BYTES  (64 * ROW_B)
#define STAGE_B  (A_BYTES + 128 * ROW_B)   // 18432
#define DYN_SMEM (4 * STAGE_B)

template <int IN_DIM>
__global__ __launch_bounds__(256, 1)
void lstm_step_mma(const __half* __restrict__ xA, int xs,
                   const __half* __restrict__ hA,
                   const __half* __restrict__ Wpk,
                   const float* __restrict__ bs,
                   float* __restrict__ cst,
                   __half* __restrict__ h_out)
{
    constexpr int K = IN_DIM + HIDDEN;
    constexpr int T = K / 32;

    extern __shared__ char smem[];

    const int tid  = threadIdx.x;
    const int bn   = blockIdx.x, bm = blockIdx.y;
    const int w    = tid >> 5, lane = tid & 31;
    const int g    = lane >> 2, tg = lane & 3;
    const int wm0  = (w >> 2) * 32;
    const int wn0  = (w & 3) * 32;

    auto issue = [&](int t) {
        const int s = t & 3;
        char* aB = smem + s * STAGE_B;
        char* bB = aB + A_BYTES;
        const int k0 = t * 32;
        const __half* sA;
        int stride;
        if (k0 < IN_DIM) { sA = xA + k0;            stride = xs;     }
        else             { sA = hA + (k0 - IN_DIM); stride = HIDDEN; }
        {   // A: 64 rows x 4 chunks = 256
            int row = tid >> 2, c = tid & 3;
            cpa16(smem_u32(aB + row * ROW_B + ((row >> 2) & 1) * 16 + c * 16),
                  sA + (bm * 64 + row) * stride + c * 8);
        }
#pragma unroll
        for (int p = 0; p < 2; ++p) {   // B: 128 rows x 4 chunks = 512
            int i   = tid + p * 256;
            int row = i >> 2, c = i & 3;
            cpa16(smem_u32(bB + row * ROW_B + ((row >> 2) & 1) * 16 + c * 16),
                  Wpk + (bn * 128 + row) * K + k0 + c * 8);
        }
        cpa_commit();
    };

    float acc[2][4][4];
#pragma unroll
    for (int mf = 0; mf < 2; ++mf)
#pragma unroll
        for (int nf = 0; nf < 4; ++nf)
#pragma unroll
            for (int q = 0; q < 4; ++q) acc[mf][nf][q] = 0.f;

    issue(0); issue(1); issue(2);

    for (int t = 0; t < T; ++t) {
        if (t < T - 2) asm volatile("cp.async.wait_group 2;" ::: "memory");
        else           asm volatile("cp.async.wait_group 0;" ::: "memory");
        __syncthreads();
        if (t + 3 < T) issue(t + 3);

        const int s = t & 3;
        const char* As = smem + s * STAGE_B;
        const char* Bs = As + A_BYTES;

#pragma unroll
        for (int ks = 0; ks < 2; ++ks) {
            const int kb = ks * 32 + 4 * tg;
            uint32_t a[2][4];
#pragma unroll
            for (int mf = 0; mf < 2; ++mf) {
                const int r0 = wm0 + mf * 16 + g;
                const int r1 = r0 + 8;
                const char* p0 = As + r0 * ROW_B + ((r0 >> 2) & 1) * 16 + kb;
                const char* p1 = As + r1 * ROW_B + ((r1 >> 2) & 1) * 16 + kb;
                a[mf][0] = *(const uint32_t*)p0;
                a[mf][1] = *(const uint32_t*)p1;
                a[mf][2] = *(const uint32_t*)(p0 + 16);
                a[mf][3] = *(const uint32_t*)(p1 + 16);
            }
#pragma unroll
            for (int nf = 0; nf < 4; ++nf) {
                const int nr = wn0 + nf * 8 + g;
                const char* pb = Bs + nr * ROW_B + ((nr >> 2) & 1) * 16 + kb;
                uint32_t b0 = *(const uint32_t*)pb;
                uint32_t b1 = *(const uint32_t*)(pb + 16);
                mma_f16(acc[0][nf], a[0], b0, b1);
                mma_f16(acc[1][nf], a[1], b0, b1);
            }
        }
    }

    // ---- epilogue: accs -> SMEM z-tile [64][132] -> fused LSTM cell ----
    __syncthreads();
    float* zs = (float*)smem;
#pragma unroll
    for (int mf = 0; mf < 2; ++mf)
#pragma unroll
        for (int nf = 0; nf < 4; ++nf) {
            int r = wm0 + mf * 16 + g;
            int c = wn0 + nf * 8 + 2 * tg;
            *(float2*)&zs[r * 132 + c]       = make_float2(acc[mf][nf][0], acc[mf][nf][1]);
            *(float2*)&zs[(r + 8) * 132 + c] = make_float2(acc[mf][nf][2], acc[mf][nf][3]);
        }
    __syncthreads();

#pragma unroll
    for (int p = 0; p < 8; ++p) {
        int idx = tid + p * 256;                  // 2048 = 64 rows x 32 j
        int bl = idx >> 5, jl = idx & 31;
        int b  = bm * 64 + bl;
        int j  = bn * 32 + jl;
        float4 z4 = *(float4*)&zs[bl * 132 + jl * 4];
        float4 b4 = *(const float4*)&bs[(bn * 32 + jl) * 4];
        float zi = z4.x + b4.x;
        float zf = z4.y + b4.y;
        float zg = z4.z + b4.z;
        float zo = z4.w + b4.w;
        float cn = fsigmoid(zf) * cst[b * HIDDEN + j] + fsigmoid(zi) * ftanh(zg);
        cst[b * HIDDEN + j]   = cn;
        h_out[b * HIDDEN + j] = __float2half_rn(fsigmoid(zo) * ftanh(cn));
    }
}

// ---------------------------------------------------------------------------
// Decoder heads
// ---------------------------------------------------------------------------
__global__ __launch_bounds__(256)
void dec_fc(const __half* __restrict__ h1,
            const float* __restrict__ fc1_w, const float* __restrict__ fc1_b,
            const float* __restrict__ fc4_w, const float* __restrict__ fc4_b,
            float* __restrict__ out, int t, __half* __restrict__ decx)
{
    __shared__ float sh[HIDDEN];
    const int b = blockIdx.x;
    for (int i = threadIdx.x; i < HIDDEN; i += blockDim.x)
        sh[i] = __half2float(h1[b * HIDDEN + i]);
    __syncthreads();

    const int warp = threadIdx.x >> 5;
    const int lane = threadIdx.x & 31;
    for (int o = warp; o < 1 + NFEAT; o += 8) {
        const float* w = (o == 0) ? fc1_w : (fc4_w + (o - 1) * HIDDEN);
        float s = 0.f;
#pragma unroll 4
        for (int k = lane; k < HIDDEN; k += 32) s += sh[k] * w[k];
#pragma unroll
        for (int off = 16; off; off >>= 1) s += __shfl_down_sync(0xffffffffu, s, off);
        if (lane == 0) {
            if (o == 0) out[b * HORIZONS + t] = s + fc1_b[0];
            else        decx[b * NFEAT + (o - 1)] = __float2half_rn(s + fc4_b[o - 1]);
        }
    }
}

// ---------------------------------------------------------------------------
extern "C" void kernel_launch(void* const* d_in, const int* in_sizes, int n_in,
                              void* d_out, int out_size)
{
    const int wb = (in_sizes[2] == 1) ? 3 : 2;

    const float* src = (const float*)d_in[0];
    const float* W[16];
    for (int i = 0; i < 16; i++) W[i] = (const float*)d_in[wb + i];
    const float* fc1_w = (const float*)d_in[wb + 16];
    const float* fc1_b = (const float*)d_in[wb + 17];
    const float* fc4_w = (const float*)d_in[wb + 18];
    const float* fc4_b = (const float*)d_in[wb + 19];
    float* out = (float*)d_out;

    unsigned char* S = nullptr;
    cudaGetSymbolAddress((void**)&S, g_scratch);

    __half* WP[4] = {(__half*)(S + OFF_WP0), (__half*)(S + OFF_WP1),
                     (__half*)(S + OFF_WP2), (__half*)(S + OFF_WP3)};
    float*  BS   = (float*)(S + OFF_BS);
    __half* Hst  = (__half*)(S + OFF_H);
    float*  Cst  = (float*)(S + OFF_C);
    __half* xh   = (__half*)(S + OFF_XH);
    __half* decx = (__half*)(S + OFF_DECX);

    cudaFuncSetAttribute(lstm_step_mma<NFEAT>,
                         cudaFuncAttributeMaxDynamicSharedMemorySize, DYN_SMEM);
    cudaFuncSetAttribute(lstm_step_mma<HIDDEN>,
                         cudaFuncAttributeMaxDynamicSharedMemorySize, DYN_SMEM);

    const int in_dims[4] = {NFEAT, HIDDEN, NFEAT, HIDDEN};
    const int k_tot[4]   = {NFEAT + HIDDEN, 2 * HIDDEN, NFEAT + HIDDEN, 2 * HIDDEN};
    const int wp_elems[4] = {544 * 2048, 1024 * 2048, 544 * 2048, 1024 * 2048};

    for (int l = 0; l < 4; l++) {
        pack_weights<<<(wp_elems[l] + 255) / 256, 256>>>(W[l * 4 + 0], W[l * 4 + 1],
                                                         in_dims[l], k_tot[l], WP[l], wp_elems[l]);
        pack_bias<<<(NGATE + 255) / 256, 256>>>(W[l * 4 + 2], W[l * 4 + 3], BS + l * NGATE);
    }

    convert_src<<<(LAGS * BATCH * NFEAT + 255) / 256, 256>>>(src, xh);
    zero_h<<<(2 * 2 * BATCH * HIDDEN + 255) / 256, 256>>>(Hst, 2 * 2 * BATCH * HIDDEN);
    zero_f<<<(2 * BATCH * HIDDEN + 255) / 256, 256>>>(Cst, 2 * BATCH * HIDDEN);

    dim3 grid(NGATE / 128, BATCH / 64);  // (16, 8)
    const int BH = BATCH * HIDDEN;

    for (int t = 0; t < LAGS; t++) {
        const __half* h0_in  = Hst + (0 * 2 + (t & 1)) * BH;
        __half*       h0_out = Hst + (0 * 2 + ((t + 1) & 1)) * BH;
        const __half* h1_in  = Hst + (2 + (t & 1)) * BH;
        __half*       h1_out = Hst + (2 + ((t + 1) & 1)) * BH;

        lstm_step_mma<NFEAT><<<grid, 256, DYN_SMEM>>>(xh + t * BATCH * NFEAT, NFEAT,
                                                      h0_in, WP[0], BS + 0 * NGATE,
                                                      Cst + 0 * BH, h0_out);
        lstm_step_mma<HIDDEN><<<grid, 256, DYN_SMEM>>>(h0_out, HIDDEN,
                                                       h1_in, WP[1], BS + 1 * NGATE,
                                                       Cst + 1 * BH, h1_out);
    }

    init_decx<<<(BATCH * NFEAT + 255) / 256, 256>>>(src, decx);

    for (int tt = 0; tt < HORIZONS; tt++) {
        int t = LAGS + tt;
        const __half* h0_in  = Hst + (0 * 2 + (t & 1)) * BH;
        __half*       h0_out = Hst + (0 * 2 + ((t + 1) & 1)) * BH;
        const __half* h1_in  = Hst + (2 + (t & 1)) * BH;
        __half*       h1_out = Hst + (2 + ((t + 1) & 1)) * BH;

        lstm_step_mma<NFEAT><<<grid, 256, DYN_SMEM>>>(decx, NFEAT,
                                                      h0_in, WP[2], BS + 2 * NGATE,
                                                      Cst + 0 * BH, h0_out);
        lstm_step_mma<HIDDEN><<<grid, 256, DYN_SMEM>>>(h0_out, HIDDEN,
                                                       h1_in, WP[3], BS + 3 * NGATE,
                                                       Cst + 1 * BH, h1_out);
        dec_fc<<<BATCH, 256>>>(h1_out, fc1_w, fc1_b, fc4_w, fc4_b, out, tt, decx);
    }
}